// round 6
// baseline (speedup 1.0000x reference)
#include <cuda_runtime.h>
#include <cuda_bf16.h>

#define BS   128
#define OBJ  512
#define RNN  1024
#define HID  512
#define KCHUNKS 32   // k-chunks of 32

// GEMM partials, layout [chunk][hid][bs] -> coalesced stores. 8MB, L2-resident.
__device__ float g_part[KCHUNKS * HID * BS];
// Reduced att_h + bias, layout [hid][bs] (256KB, L2-resident).
__device__ float g_atth[HID * BS];
// Score scratch: [b][obj]
__device__ float g_scores[BS * OBJ];

__device__ __forceinline__ float tanh_fast(float x) {
    float y;
    asm("tanh.approx.f32 %0, %1;" : "=f"(y) : "f"(x));
    return y;
}

// ---------------- GEMM: att_h partials ----------------
// grid (16 n-tiles of 32, 32 k-chunks of 32), 256 threads, single stage.
// Microtile: 4 consecutive b x 4 consecutive n -> 2x LDS.128 + 16 FFMA per
// k-iter; epilogue 4x STG.128, warp-contiguous.
// part[c][n][b] = sum_{k in chunk c} h[b][k] * W[n][k]
__global__ __launch_bounds__(256) void gemm_kernel(
    const float* __restrict__ h, const float* __restrict__ W)
{
    __shared__ float h_s[32][132];   // [k][b], +4 pad
    __shared__ float w_s[32][36];    // [k][j], +4 pad
    const int n0 = blockIdx.x * 32;
    const int k0 = blockIdx.y * 32;
    const int t  = threadIdx.x;
    const int tm = t & 31;    // b group: 4 consecutive rows tm*4..tm*4+3
    const int tn = t >> 5;    // n group: 4 consecutive cols tn*4..tn*4+3

    // Front-batch all 5 global loads (MLP=5)
    const int hb = t >> 3, hk = t & 7;   // h: row hb+32r, float4 slot hk
    float4 hv[4], wv;
    #pragma unroll
    for (int r = 0; r < 4; ++r)
        hv[r] = *(const float4*)(h + (hb + 32 * r) * RNN + k0 + hk * 4);
    const int wj = t >> 3, wk = t & 7;
    wv = *(const float4*)(W + (n0 + wj) * RNN + k0 + wk * 4);

    #pragma unroll
    for (int r = 0; r < 4; ++r) {
        h_s[hk*4+0][hb + 32*r] = hv[r].x; h_s[hk*4+1][hb + 32*r] = hv[r].y;
        h_s[hk*4+2][hb + 32*r] = hv[r].z; h_s[hk*4+3][hb + 32*r] = hv[r].w;
    }
    w_s[wk*4+0][wj] = wv.x; w_s[wk*4+1][wj] = wv.y;
    w_s[wk*4+2][wj] = wv.z; w_s[wk*4+3][wj] = wv.w;
    __syncthreads();

    float acc[4][4] = {};   // [b_comp][n_comp]
    #pragma unroll 8
    for (int k = 0; k < 32; ++k) {
        float4 a  = *(const float4*)&h_s[k][tm * 4];
        float4 bv = *(const float4*)&w_s[k][tn * 4];
        acc[0][0] += a.x*bv.x; acc[0][1] += a.x*bv.y; acc[0][2] += a.x*bv.z; acc[0][3] += a.x*bv.w;
        acc[1][0] += a.y*bv.x; acc[1][1] += a.y*bv.y; acc[1][2] += a.y*bv.z; acc[1][3] += a.y*bv.w;
        acc[2][0] += a.z*bv.x; acc[2][1] += a.z*bv.y; acc[2][2] += a.z*bv.z; acc[2][3] += a.z*bv.w;
        acc[3][0] += a.w*bv.x; acc[3][1] += a.w*bv.y; acc[3][2] += a.w*bv.z; acc[3][3] += a.w*bv.w;
    }

    // Epilogue: per (j), a warp's 32 lanes write 32 contiguous float4.
    float* outp = g_part + blockIdx.y * (HID * BS);
    #pragma unroll
    for (int j = 0; j < 4; ++j) {
        float4 v = make_float4(acc[0][j], acc[1][j], acc[2][j], acc[3][j]);
        *(float4*)(outp + (n0 + tn * 4 + j) * BS + tm * 4) = v;
    }
}

// ---------------- Reduce: sum partials + bias ----------------
// grid 256 x 256; one (n,b) element per thread, fully coalesced (8MB read).
__global__ __launch_bounds__(256) void reduce_kernel(
    const float* __restrict__ b_h2att)
{
    const int tid = blockIdx.x * 256 + threadIdx.x;   // n*BS + b
    float s = b_h2att[tid >> 7];   // warp-uniform
    #pragma unroll
    for (int c = 0; c < KCHUNKS; ++c)
        s += g_part[c * (HID * BS) + tid];
    g_atth[tid] = s;
}

// ---------------- Scores: tanh + rank-1 dot ----------------
// grid 512 (= 128 b x 4 obj-chunks of 128), 256 threads. Streams att_feats
// with __ldcs, MLP=8 per warp. b_alpha dropped (cancels in softmax).
__global__ __launch_bounds__(256) void scores_kernel(
    const float* __restrict__ att_feats,
    const float* __restrict__ w_alpha)
{
    const int b     = blockIdx.x >> 2;
    const int chunk = blockIdx.x & 3;
    __shared__ float ah[HID];
    __shared__ float wa[HID];
    const int t = threadIdx.x;

    #pragma unroll
    for (int e = 0; e < 2; ++e) {
        int idx = t + 256 * e;
        ah[idx] = g_atth[idx * BS + b];   // L2-resident, 2KB total
        wa[idx] = w_alpha[idx];
    }
    __syncthreads();

    const int w = t >> 5, lane = t & 31;
    const float4* base = (const float4*)(att_feats
                         + (size_t)b * OBJ * HID + (size_t)chunk * 128 * HID);
    const float4* ah4  = (const float4*)ah;
    const float4* wa4  = (const float4*)wa;

    for (int o = w; o < 128; o += 16) {
        const float4* r0 = base + o       * (HID / 4);
        const float4* r1 = base + (o + 8) * (HID / 4);
        float4 f0[4], f1[4];
        #pragma unroll
        for (int i = 0; i < 4; ++i) {
            f0[i] = __ldcs(r0 + lane + 32 * i);
            f1[i] = __ldcs(r1 + lane + 32 * i);
        }
        float s0 = 0.f, s1 = 0.f;
        #pragma unroll
        for (int i = 0; i < 4; ++i) {
            int idx = lane + 32 * i;
            float4 a  = ah4[idx];
            float4 wv = wa4[idx];
            s0 += tanh_fast(f0[i].x + a.x) * wv.x;
            s0 += tanh_fast(f0[i].y + a.y) * wv.y;
            s0 += tanh_fast(f0[i].z + a.z) * wv.z;
            s0 += tanh_fast(f0[i].w + a.w) * wv.w;
            s1 += tanh_fast(f1[i].x + a.x) * wv.x;
            s1 += tanh_fast(f1[i].y + a.y) * wv.y;
            s1 += tanh_fast(f1[i].z + a.z) * wv.z;
            s1 += tanh_fast(f1[i].w + a.w) * wv.w;
        }
        #pragma unroll
        for (int d = 16; d; d >>= 1) {
            s0 += __shfl_xor_sync(0xffffffffu, s0, d);
            s1 += __shfl_xor_sync(0xffffffffu, s1, d);
        }
        if (lane == 0) {
            g_scores[b * OBJ + chunk * 128 + o]     = s0;
            g_scores[b * OBJ + chunk * 128 + o + 8] = s1;
        }
    }
}

// ---------------- Masked softmax ----------------
// grid 128, 256 threads x 2 elems. softmax->mask->renorm collapses to a
// masked softmax; b_alpha cancels.
__global__ __launch_bounds__(256) void softmax_kernel(
    const int* __restrict__ att_masks, float* __restrict__ out)
{
    const int b = blockIdx.x;
    const int t = threadIdx.x;
    const int w = t >> 5, lane = t & 31;
    __shared__ float red[8];

    float s0 = g_scores[b * OBJ + t];
    float s1 = g_scores[b * OBJ + t + 256];

    float v = fmaxf(s0, s1);
    #pragma unroll
    for (int d = 16; d; d >>= 1) v = fmaxf(v, __shfl_xor_sync(0xffffffffu, v, d));
    if (lane == 0) red[w] = v;
    __syncthreads();
    if (w == 0) {
        float m = red[lane & 7];
        #pragma unroll
        for (int d = 4; d; d >>= 1) m = fmaxf(m, __shfl_xor_sync(0xffffffffu, m, d));
        if (lane == 0) red[0] = m;
    }
    __syncthreads();
    const float mx = red[0];

    float m0 = (float)att_masks[b * OBJ + t];
    float m1 = (float)att_masks[b * OBJ + t + 256];
    float e0 = m0 * __expf(s0 - mx);
    float e1 = m1 * __expf(s1 - mx);
    float s = e0 + e1;
    #pragma unroll
    for (int d = 16; d; d >>= 1) s += __shfl_xor_sync(0xffffffffu, s, d);
    __syncthreads();
    if (lane == 0) red[w] = s;
    __syncthreads();
    if (w == 0) {
        float z = red[lane & 7];
        #pragma unroll
        for (int d = 4; d; d >>= 1) z += __shfl_xor_sync(0xffffffffu, z, d);
        if (lane == 0) red[0] = z;
    }
    __syncthreads();
    const float inv = 1.f / red[0];
    out[b * OBJ + t]       = e0 * inv;
    out[b * OBJ + t + 256] = e1 * inv;
}

extern "C" void kernel_launch(void* const* d_in, const int* in_sizes, int n_in,
                              void* d_out, int out_size) {
    const float* h         = (const float*)d_in[0];
    const float* att_feats = (const float*)d_in[1];
    const int*   att_masks = (const int*)  d_in[2];
    const float* W_h2att   = (const float*)d_in[3];
    const float* b_h2att   = (const float*)d_in[4];
    const float* w_alpha   = (const float*)d_in[5];
    // d_in[6] = b_alpha: cancels in softmax, unused.
    float* out = (float*)d_out;

    gemm_kernel<<<dim3(16, 32), 256>>>(h, W_h2att);
    reduce_kernel<<<256, 256>>>(b_h2att);
    scores_kernel<<<512, 256>>>(att_feats, w_alpha);
    softmax_kernel<<<BS, 256>>>(att_masks, out);
}